// round 12
// baseline (speedup 1.0000x reference)
#include <cuda_runtime.h>
#include <math.h>

#define BB 8
#define TT 1024
#define DD 1024
#define HH 16
#define DH 64
#define D3 3072

// Scratch buffers (device globals: no allocation allowed)
__device__ float g_qkv[BB * TT * D3];    // [B,T,3D]
__device__ float g_attn[BB * TT * DD];   // [B,T,D]

// ---------------------------------------------------------------------------
// SGEMM + bias: C[M,N] = A[M,K] @ B[K,N] + bias[N]
// 128x128 block tile, BK=8, 256 threads, 8x8 microtile, software-pipelined
// global loads. Requires M%128==0, N%128==0, K%8==0 (true for all our shapes).
// ---------------------------------------------------------------------------
__global__ __launch_bounds__(256) void sgemm_bias(const float* __restrict__ A,
                                                  const float* __restrict__ Bm,
                                                  const float* __restrict__ bias,
                                                  float* __restrict__ C,
                                                  int M, int N, int K)
{
    __shared__ float As[8][128];   // transposed: As[k][m]
    __shared__ float Bs[8][128];   // Bs[k][n]

    const int t  = threadIdx.x;
    const int tx = t & 15;
    const int ty = t >> 4;
    const int m0 = blockIdx.y * 128;
    const int n0 = blockIdx.x * 128;

    float acc[8][8];
#pragma unroll
    for (int i = 0; i < 8; i++)
#pragma unroll
        for (int j = 0; j < 8; j++) acc[i][j] = 0.0f;

    const int arow = t >> 1;          // 0..127
    const int acol = (t & 1) * 4;     // 0 or 4
    const int brow = t >> 5;          // 0..7
    const int bcol = (t & 31) * 4;    // 0..124

    const float* Ap = A  + (size_t)(m0 + arow) * K + acol;
    const float* Bp = Bm + (size_t)brow * N + n0 + bcol;

    // prefetch first tiles
    float4 av = *(const float4*)(Ap);
    float4 bv = *(const float4*)(Bp);

    for (int k0 = 0; k0 < K; k0 += 8) {
        As[acol + 0][arow] = av.x;
        As[acol + 1][arow] = av.y;
        As[acol + 2][arow] = av.z;
        As[acol + 3][arow] = av.w;
        *(float4*)&Bs[brow][bcol] = bv;
        __syncthreads();

        if (k0 + 8 < K) {
            av = *(const float4*)(Ap + (k0 + 8));
            bv = *(const float4*)(Bp + (size_t)(k0 + 8) * N);
        }

#pragma unroll
        for (int kk = 0; kk < 8; kk++) {
            float a[8], b[8];
            *(float4*)&a[0] = *(const float4*)&As[kk][ty * 4];
            *(float4*)&a[4] = *(const float4*)&As[kk][64 + ty * 4];
            *(float4*)&b[0] = *(const float4*)&Bs[kk][tx * 4];
            *(float4*)&b[4] = *(const float4*)&Bs[kk][64 + tx * 4];
#pragma unroll
            for (int i = 0; i < 8; i++)
#pragma unroll
                for (int j = 0; j < 8; j++)
                    acc[i][j] += a[i] * b[j];
        }
        __syncthreads();
    }

    // epilogue: add bias, float4 stores
#pragma unroll
    for (int ih = 0; ih < 2; ih++) {
#pragma unroll
        for (int ii = 0; ii < 4; ii++) {
            const int i = ih * 4 + ii;
            const int r = m0 + ih * 64 + ty * 4 + ii;
#pragma unroll
            for (int jh = 0; jh < 2; jh++) {
                const int c = n0 + jh * 64 + tx * 4;
                float4 bvv = *(const float4*)&bias[c];
                float4 res;
                res.x = acc[i][jh * 4 + 0] + bvv.x;
                res.y = acc[i][jh * 4 + 1] + bvv.y;
                res.z = acc[i][jh * 4 + 2] + bvv.z;
                res.w = acc[i][jh * 4 + 3] + bvv.w;
                *(float4*)&C[(size_t)r * N + c] = res;
            }
        }
    }
}

// ---------------------------------------------------------------------------
// Flash attention, fp32, one CTA per (b, h, 64-row q tile).
// qkv layout [B,T,3D]; q at col h*64, k at D + h*64, v at 2D + h*64.
// Online softmax. Cols >= len masked (-1e30 -> exp underflows to exact 0);
// rows >= len written as 0 (matches reference softmax*mask semantics).
// ---------------------------------------------------------------------------
#define AP 68   // padded row stride (floats), keeps float4 alignment, de-conflicts

__global__ __launch_bounds__(256) void flash_attn(const float* __restrict__ qkv,
                                                  const int* __restrict__ lengths,
                                                  float* __restrict__ out)
{
    extern __shared__ float sm[];
    float* QsT = sm;                 // [64][AP]  (d-major: QsT[d*AP + r])
    float* KsT = sm + 64 * AP;       // [64][AP]  (d-major), reused as P [c][r]
    float* Vs  = sm + 2 * 64 * AP;   // [64][AP]  (c-major: Vs[c*AP + d])

    const int t  = threadIdx.x;
    const int tx = t & 15;           // kv-col group / Dh-col group
    const int ty = t >> 4;           // q-row group
    const int bh = blockIdx.x;
    const int b  = bh >> 4;
    const int h  = bh & 15;
    const int r0 = blockIdx.y * 64;
    const int l  = lengths[b];

    const float* base = qkv + (size_t)b * TT * D3 + h * DH;

    // ---- load Q (scaled by 1/sqrt(Dh) = 0.125), transposed into QsT[d][r]
    {
        const int lr = t >> 2;             // 0..63 row
        const int d0 = (t & 3) * 16;       // d chunk start
        const float* qp = base + (size_t)(r0 + lr) * D3 + d0;
#pragma unroll
        for (int u = 0; u < 4; u++) {
            float4 v = *(const float4*)(qp + u * 4);
            QsT[(d0 + u * 4 + 0) * AP + lr] = v.x * 0.125f;
            QsT[(d0 + u * 4 + 1) * AP + lr] = v.y * 0.125f;
            QsT[(d0 + u * 4 + 2) * AP + lr] = v.z * 0.125f;
            QsT[(d0 + u * 4 + 3) * AP + lr] = v.w * 0.125f;
        }
    }

    float m_i[4], l_i[4], o[4][4];
#pragma unroll
    for (int i = 0; i < 4; i++) {
        m_i[i] = -1e30f;
        l_i[i] = 0.0f;
#pragma unroll
        for (int j = 0; j < 4; j++) o[i][j] = 0.0f;
    }

    const int ntiles = (l + 63) >> 6;   // tiles fully past len contribute 0
    for (int kt = 0; kt < ntiles; kt++) {
        const int c0 = kt * 64;

        // ---- load K transposed (KsT[d][c]) and V natural (Vs[c][d])
        {
            const int lr = t >> 2;
            const int d0 = (t & 3) * 16;
            const float* kp = base + DD     + (size_t)(c0 + lr) * D3 + d0;
            const float* vp = base + 2 * DD + (size_t)(c0 + lr) * D3 + d0;
#pragma unroll
            for (int u = 0; u < 4; u++) {
                float4 kv = *(const float4*)(kp + u * 4);
                KsT[(d0 + u * 4 + 0) * AP + lr] = kv.x;
                KsT[(d0 + u * 4 + 1) * AP + lr] = kv.y;
                KsT[(d0 + u * 4 + 2) * AP + lr] = kv.z;
                KsT[(d0 + u * 4 + 3) * AP + lr] = kv.w;
                float4 vv = *(const float4*)(vp + u * 4);
                *(float4*)&Vs[lr * AP + d0 + u * 4] = vv;
            }
        }
        __syncthreads();   // K/V (and Q on iter 0) visible

        // ---- S = (Q*scale) @ K^T, 4x4 per thread
        float s[4][4];
#pragma unroll
        for (int i = 0; i < 4; i++)
#pragma unroll
            for (int j = 0; j < 4; j++) s[i][j] = 0.0f;

#pragma unroll
        for (int d = 0; d < 64; d++) {
            float4 q4 = *(const float4*)&QsT[d * AP + ty * 4];
            float4 k4 = *(const float4*)&KsT[d * AP + tx * 4];
            float qa[4] = {q4.x, q4.y, q4.z, q4.w};
            float ka[4] = {k4.x, k4.y, k4.z, k4.w};
#pragma unroll
            for (int i = 0; i < 4; i++)
#pragma unroll
                for (int j = 0; j < 4; j++)
                    s[i][j] += qa[i] * ka[j];
        }

        // ---- column mask (only possible on the last tile)
        if (c0 + 64 > l) {
#pragma unroll
            for (int j = 0; j < 4; j++) {
                if (c0 + tx * 4 + j >= l) {
#pragma unroll
                    for (int i = 0; i < 4; i++) s[i][j] = -1e30f;
                }
            }
        }

        // ---- online softmax (row spans 16 contiguous lanes -> shfl_xor <=8)
#pragma unroll
        for (int i = 0; i < 4; i++) {
            float rm = fmaxf(fmaxf(s[i][0], s[i][1]), fmaxf(s[i][2], s[i][3]));
            rm = fmaxf(rm, __shfl_xor_sync(0xffffffffu, rm, 1));
            rm = fmaxf(rm, __shfl_xor_sync(0xffffffffu, rm, 2));
            rm = fmaxf(rm, __shfl_xor_sync(0xffffffffu, rm, 4));
            rm = fmaxf(rm, __shfl_xor_sync(0xffffffffu, rm, 8));
            float mnew = fmaxf(m_i[i], rm);
            float corr = __expf(m_i[i] - mnew);
            m_i[i] = mnew;
            float rs = 0.0f;
#pragma unroll
            for (int j = 0; j < 4; j++) {
                s[i][j] = __expf(s[i][j] - mnew);
                rs += s[i][j];
            }
            rs += __shfl_xor_sync(0xffffffffu, rs, 1);
            rs += __shfl_xor_sync(0xffffffffu, rs, 2);
            rs += __shfl_xor_sync(0xffffffffu, rs, 4);
            rs += __shfl_xor_sync(0xffffffffu, rs, 8);
            l_i[i] = l_i[i] * corr + rs;
#pragma unroll
            for (int j = 0; j < 4; j++) o[i][j] *= corr;
        }

        __syncthreads();   // all reads of KsT done before overwriting with P

        // ---- store P into KsT space as P[c][r] (c-major) for the PV pass
        float* Pst = KsT;
#pragma unroll
        for (int j = 0; j < 4; j++) {
            float4 pv = make_float4(s[0][j], s[1][j], s[2][j], s[3][j]);
            *(float4*)&Pst[(tx * 4 + j) * AP + ty * 4] = pv;
        }
        __syncthreads();   // P visible

        // ---- O += P @ V
#pragma unroll
        for (int c = 0; c < 64; c++) {
            float4 p4 = *(const float4*)&Pst[c * AP + ty * 4];
            float4 v4 = *(const float4*)&Vs[c * AP + tx * 4];
            float pa[4] = {p4.x, p4.y, p4.z, p4.w};
            float va[4] = {v4.x, v4.y, v4.z, v4.w};
#pragma unroll
            for (int i = 0; i < 4; i++)
#pragma unroll
                for (int j = 0; j < 4; j++)
                    o[i][j] += pa[i] * va[j];
        }
        __syncthreads();   // PV reads done before next tile load
    }

    // ---- writeout: divide by softmax denom, zero rows >= len
    float* ob = out + (size_t)b * TT * DD + h * DH;
#pragma unroll
    for (int i = 0; i < 4; i++) {
        const int r = r0 + ty * 4 + i;
        const float inv = (r < l) ? (1.0f / l_i[i]) : 0.0f;
        float4 res = make_float4(o[i][0] * inv, o[i][1] * inv,
                                 o[i][2] * inv, o[i][3] * inv);
        *(float4*)&ob[(size_t)r * DD + tx * 4] = res;
    }
}

// ---------------------------------------------------------------------------
// Launch: qkv-proj GEMM -> flash attention -> output-proj GEMM
// ---------------------------------------------------------------------------
extern "C" void kernel_launch(void* const* d_in, const int* in_sizes, int n_in,
                              void* d_out, int out_size)
{
    const float* x      = (const float*)d_in[0];   // [8,1024,1024]
    const int*   lens   = (const int*)  d_in[1];   // [8]
    const float* w_qkv  = (const float*)d_in[2];   // [1024,3072]
    const float* b_qkv  = (const float*)d_in[3];   // [3072]
    const float* w_o    = (const float*)d_in[4];   // [1024,1024]
    const float* b_o    = (const float*)d_in[5];   // [1024]
    float*       out    = (float*)d_out;           // [8,1024,1024]

    void* qkv_ptr = nullptr;
    void* attn_ptr = nullptr;
    cudaGetSymbolAddress(&qkv_ptr, g_qkv);
    cudaGetSymbolAddress(&attn_ptr, g_attn);
    float* g_qkv_p  = (float*)qkv_ptr;
    float* g_attn_p = (float*)attn_ptr;

    const int M = BB * TT;   // 8192

    // GEMM1: [8192,1024] @ [1024,3072] + b_qkv
    {
        dim3 grid(D3 / 128, M / 128);
        sgemm_bias<<<grid, 256>>>(x, w_qkv, b_qkv, g_qkv_p, M, D3, DD);
    }

    // Flash attention: grid (B*H, T/64)
    {
        const int smem = 3 * 64 * AP * (int)sizeof(float);  // 52224 B
        cudaFuncSetAttribute(flash_attn,
                             cudaFuncAttributeMaxDynamicSharedMemorySize, smem);
        dim3 grid(BB * HH, TT / 64);
        flash_attn<<<grid, 256, smem>>>(g_qkv_p, lens, g_attn_p);
    }

    // GEMM2: [8192,1024] @ [1024,1024] + b_o -> out
    {
        dim3 grid(DD / 128, M / 128);
        sgemm_bias<<<grid, 256>>>(g_attn_p, w_o, b_o, out, M, DD, DD);
    }
}

// round 13
// speedup vs baseline: 1.0043x; 1.0043x over previous
#include <cuda_runtime.h>
#include <math.h>

#define BB 8
#define TT 1024
#define DD 1024
#define HH 16
#define DH 64
#define D3 3072

// Scratch buffers (device globals: no allocation allowed)
__device__ float g_qkv[BB * TT * D3];    // [B,T,3D]
__device__ float g_attn[BB * TT * DD];   // [B,T,D]

// ---------------------------------------------------------------------------
// SGEMM + bias: C[M,N] = A[M,K] @ B[K,N] + bias[N]
// 128x128 block tile, BK=8, 256 threads, 8x8 microtile, software-pipelined
// global loads. Requires M%128==0, N%128==0, K%8==0 (true for all our shapes).
// ---------------------------------------------------------------------------
__global__ __launch_bounds__(256) void sgemm_bias(const float* __restrict__ A,
                                                  const float* __restrict__ Bm,
                                                  const float* __restrict__ bias,
                                                  float* __restrict__ C,
                                                  int M, int N, int K)
{
    __shared__ float As[8][128];   // transposed: As[k][m]
    __shared__ float Bs[8][128];   // Bs[k][n]

    const int t  = threadIdx.x;
    const int tx = t & 15;
    const int ty = t >> 4;
    const int m0 = blockIdx.y * 128;
    const int n0 = blockIdx.x * 128;

    float acc[8][8];
#pragma unroll
    for (int i = 0; i < 8; i++)
#pragma unroll
        for (int j = 0; j < 8; j++) acc[i][j] = 0.0f;

    const int arow = t >> 1;          // 0..127
    const int acol = (t & 1) * 4;     // 0 or 4
    const int brow = t >> 5;          // 0..7
    const int bcol = (t & 31) * 4;    // 0..124

    const float* Ap = A  + (size_t)(m0 + arow) * K + acol;
    const float* Bp = Bm + (size_t)brow * N + n0 + bcol;

    // prefetch first tiles
    float4 av = *(const float4*)(Ap);
    float4 bv = *(const float4*)(Bp);

    for (int k0 = 0; k0 < K; k0 += 8) {
        As[acol + 0][arow] = av.x;
        As[acol + 1][arow] = av.y;
        As[acol + 2][arow] = av.z;
        As[acol + 3][arow] = av.w;
        *(float4*)&Bs[brow][bcol] = bv;
        __syncthreads();

        if (k0 + 8 < K) {
            av = *(const float4*)(Ap + (k0 + 8));
            bv = *(const float4*)(Bp + (size_t)(k0 + 8) * N);
        }

#pragma unroll
        for (int kk = 0; kk < 8; kk++) {
            float a[8], b[8];
            *(float4*)&a[0] = *(const float4*)&As[kk][ty * 4];
            *(float4*)&a[4] = *(const float4*)&As[kk][64 + ty * 4];
            *(float4*)&b[0] = *(const float4*)&Bs[kk][tx * 4];
            *(float4*)&b[4] = *(const float4*)&Bs[kk][64 + tx * 4];
#pragma unroll
            for (int i = 0; i < 8; i++)
#pragma unroll
                for (int j = 0; j < 8; j++)
                    acc[i][j] += a[i] * b[j];
        }
        __syncthreads();
    }

    // epilogue: add bias, float4 stores
#pragma unroll
    for (int ih = 0; ih < 2; ih++) {
#pragma unroll
        for (int ii = 0; ii < 4; ii++) {
            const int i = ih * 4 + ii;
            const int r = m0 + ih * 64 + ty * 4 + ii;
#pragma unroll
            for (int jh = 0; jh < 2; jh++) {
                const int c = n0 + jh * 64 + tx * 4;
                float4 bvv = *(const float4*)&bias[c];
                float4 res;
                res.x = acc[i][jh * 4 + 0] + bvv.x;
                res.y = acc[i][jh * 4 + 1] + bvv.y;
                res.z = acc[i][jh * 4 + 2] + bvv.z;
                res.w = acc[i][jh * 4 + 3] + bvv.w;
                *(float4*)&C[(size_t)r * N + c] = res;
            }
        }
    }
}

// ---------------------------------------------------------------------------
// Flash attention, fp32, one CTA per (b, h, 64-row q tile).
// qkv layout [B,T,3D]; q at col h*64, k at D + h*64, v at 2D + h*64.
// Online softmax. Cols >= len masked (-1e30 -> exp underflows to exact 0);
// rows >= len written as 0 (matches reference softmax*mask semantics).
// ---------------------------------------------------------------------------
#define AP 68   // padded row stride (floats), keeps float4 alignment, de-conflicts

__global__ __launch_bounds__(256) void flash_attn(const float* __restrict__ qkv,
                                                  const int* __restrict__ lengths,
                                                  float* __restrict__ out)
{
    extern __shared__ float sm[];
    float* QsT = sm;                 // [64][AP]  (d-major: QsT[d*AP + r])
    float* KsT = sm + 64 * AP;       // [64][AP]  (d-major), reused as P [c][r]
    float* Vs  = sm + 2 * 64 * AP;   // [64][AP]  (c-major: Vs[c*AP + d])

    const int t  = threadIdx.x;
    const int tx = t & 15;           // kv-col group / Dh-col group
    const int ty = t >> 4;           // q-row group
    const int bh = blockIdx.x;
    const int b  = bh >> 4;
    const int h  = bh & 15;
    const int r0 = blockIdx.y * 64;
    const int l  = lengths[b];

    const float* base = qkv + (size_t)b * TT * D3 + h * DH;

    // ---- load Q (scaled by 1/sqrt(Dh) = 0.125), transposed into QsT[d][r]
    {
        const int lr = t >> 2;             // 0..63 row
        const int d0 = (t & 3) * 16;       // d chunk start
        const float* qp = base + (size_t)(r0 + lr) * D3 + d0;
#pragma unroll
        for (int u = 0; u < 4; u++) {
            float4 v = *(const float4*)(qp + u * 4);
            QsT[(d0 + u * 4 + 0) * AP + lr] = v.x * 0.125f;
            QsT[(d0 + u * 4 + 1) * AP + lr] = v.y * 0.125f;
            QsT[(d0 + u * 4 + 2) * AP + lr] = v.z * 0.125f;
            QsT[(d0 + u * 4 + 3) * AP + lr] = v.w * 0.125f;
        }
    }

    float m_i[4], l_i[4], o[4][4];
#pragma unroll
    for (int i = 0; i < 4; i++) {
        m_i[i] = -1e30f;
        l_i[i] = 0.0f;
#pragma unroll
        for (int j = 0; j < 4; j++) o[i][j] = 0.0f;
    }

    const int ntiles = (l + 63) >> 6;   // tiles fully past len contribute 0
    for (int kt = 0; kt < ntiles; kt++) {
        const int c0 = kt * 64;

        // ---- load K transposed (KsT[d][c]) and V natural (Vs[c][d])
        {
            const int lr = t >> 2;
            const int d0 = (t & 3) * 16;
            const float* kp = base + DD     + (size_t)(c0 + lr) * D3 + d0;
            const float* vp = base + 2 * DD + (size_t)(c0 + lr) * D3 + d0;
#pragma unroll
            for (int u = 0; u < 4; u++) {
                float4 kv = *(const float4*)(kp + u * 4);
                KsT[(d0 + u * 4 + 0) * AP + lr] = kv.x;
                KsT[(d0 + u * 4 + 1) * AP + lr] = kv.y;
                KsT[(d0 + u * 4 + 2) * AP + lr] = kv.z;
                KsT[(d0 + u * 4 + 3) * AP + lr] = kv.w;
                float4 vv = *(const float4*)(vp + u * 4);
                *(float4*)&Vs[lr * AP + d0 + u * 4] = vv;
            }
        }
        __syncthreads();   // K/V (and Q on iter 0) visible

        // ---- S = (Q*scale) @ K^T, 4x4 per thread
        float s[4][4];
#pragma unroll
        for (int i = 0; i < 4; i++)
#pragma unroll
            for (int j = 0; j < 4; j++) s[i][j] = 0.0f;

#pragma unroll
        for (int d = 0; d < 64; d++) {
            float4 q4 = *(const float4*)&QsT[d * AP + ty * 4];
            float4 k4 = *(const float4*)&KsT[d * AP + tx * 4];
            float qa[4] = {q4.x, q4.y, q4.z, q4.w};
            float ka[4] = {k4.x, k4.y, k4.z, k4.w};
#pragma unroll
            for (int i = 0; i < 4; i++)
#pragma unroll
                for (int j = 0; j < 4; j++)
                    s[i][j] += qa[i] * ka[j];
        }

        // ---- column mask (only possible on the last tile)
        if (c0 + 64 > l) {
#pragma unroll
            for (int j = 0; j < 4; j++) {
                if (c0 + tx * 4 + j >= l) {
#pragma unroll
                    for (int i = 0; i < 4; i++) s[i][j] = -1e30f;
                }
            }
        }

        // ---- online softmax (row spans 16 contiguous lanes -> shfl_xor <=8)
#pragma unroll
        for (int i = 0; i < 4; i++) {
            float rm = fmaxf(fmaxf(s[i][0], s[i][1]), fmaxf(s[i][2], s[i][3]));
            rm = fmaxf(rm, __shfl_xor_sync(0xffffffffu, rm, 1));
            rm = fmaxf(rm, __shfl_xor_sync(0xffffffffu, rm, 2));
            rm = fmaxf(rm, __shfl_xor_sync(0xffffffffu, rm, 4));
            rm = fmaxf(rm, __shfl_xor_sync(0xffffffffu, rm, 8));
            float mnew = fmaxf(m_i[i], rm);
            float corr = __expf(m_i[i] - mnew);
            m_i[i] = mnew;
            float rs = 0.0f;
#pragma unroll
            for (int j = 0; j < 4; j++) {
                s[i][j] = __expf(s[i][j] - mnew);
                rs += s[i][j];
            }
            rs += __shfl_xor_sync(0xffffffffu, rs, 1);
            rs += __shfl_xor_sync(0xffffffffu, rs, 2);
            rs += __shfl_xor_sync(0xffffffffu, rs, 4);
            rs += __shfl_xor_sync(0xffffffffu, rs, 8);
            l_i[i] = l_i[i] * corr + rs;
#pragma unroll
            for (int j = 0; j < 4; j++) o[i][j] *= corr;
        }

        __syncthreads();   // all reads of KsT done before overwriting with P

        // ---- store P into KsT space as P[c][r] (c-major) for the PV pass
        float* Pst = KsT;
#pragma unroll
        for (int j = 0; j < 4; j++) {
            float4 pv = make_float4(s[0][j], s[1][j], s[2][j], s[3][j]);
            *(float4*)&Pst[(tx * 4 + j) * AP + ty * 4] = pv;
        }
        __syncthreads();   // P visible

        // ---- O += P @ V
#pragma unroll
        for (int c = 0; c < 64; c++) {
            float4 p4 = *(const float4*)&Pst[c * AP + ty * 4];
            float4 v4 = *(const float4*)&Vs[c * AP + tx * 4];
            float pa[4] = {p4.x, p4.y, p4.z, p4.w};
            float va[4] = {v4.x, v4.y, v4.z, v4.w};
#pragma unroll
            for (int i = 0; i < 4; i++)
#pragma unroll
                for (int j = 0; j < 4; j++)
                    o[i][j] += pa[i] * va[j];
        }
        __syncthreads();   // PV reads done before next tile load
    }

    // ---- writeout: divide by softmax denom, zero rows >= len
    float* ob = out + (size_t)b * TT * DD + h * DH;
#pragma unroll
    for (int i = 0; i < 4; i++) {
        const int r = r0 + ty * 4 + i;
        const float inv = (r < l) ? (1.0f / l_i[i]) : 0.0f;
        float4 res = make_float4(o[i][0] * inv, o[i][1] * inv,
                                 o[i][2] * inv, o[i][3] * inv);
        *(float4*)&ob[(size_t)r * DD + tx * 4] = res;
    }
}

// ---------------------------------------------------------------------------
// Launch: qkv-proj GEMM -> flash attention -> output-proj GEMM
// ---------------------------------------------------------------------------
extern "C" void kernel_launch(void* const* d_in, const int* in_sizes, int n_in,
                              void* d_out, int out_size)
{
    const float* x      = (const float*)d_in[0];   // [8,1024,1024]
    const int*   lens   = (const int*)  d_in[1];   // [8]
    const float* w_qkv  = (const float*)d_in[2];   // [1024,3072]
    const float* b_qkv  = (const float*)d_in[3];   // [3072]
    const float* w_o    = (const float*)d_in[4];   // [1024,1024]
    const float* b_o    = (const float*)d_in[5];   // [1024]
    float*       out    = (float*)d_out;           // [8,1024,1024]

    void* qkv_ptr = nullptr;
    void* attn_ptr = nullptr;
    cudaGetSymbolAddress(&qkv_ptr, g_qkv);
    cudaGetSymbolAddress(&attn_ptr, g_attn);
    float* g_qkv_p  = (float*)qkv_ptr;
    float* g_attn_p = (float*)attn_ptr;

    const int M = BB * TT;   // 8192

    // GEMM1: [8192,1024] @ [1024,3072] + b_qkv
    {
        dim3 grid(D3 / 128, M / 128);
        sgemm_bias<<<grid, 256>>>(x, w_qkv, b_qkv, g_qkv_p, M, D3, DD);
    }

    // Flash attention: grid (B*H, T/64)
    {
        const int smem = 3 * 64 * AP * (int)sizeof(float);  // 52224 B
        cudaFuncSetAttribute(flash_attn,
                             cudaFuncAttributeMaxDynamicSharedMemorySize, smem);
        dim3 grid(BB * HH, TT / 64);
        flash_attn<<<grid, 256, smem>>>(g_qkv_p, lens, g_attn_p);
    }

    // GEMM2: [8192,1024] @ [1024,1024] + b_o -> out
    {
        dim3 grid(DD / 128, M / 128);
        sgemm_bias<<<grid, 256>>>(g_attn_p, w_o, b_o, out, M, DD, DD);
    }
}

// round 14
// speedup vs baseline: 1.0049x; 1.0005x over previous
#include <cuda_runtime.h>
#include <math.h>

#define BB 8
#define TT 1024
#define DD 1024
#define HH 16
#define DH 64
#define D3 3072

// Scratch buffers (device globals: no allocation allowed)
__device__ float g_qkv[BB * TT * D3];    // [B,T,3D]
__device__ float g_attn[BB * TT * DD];   // [B,T,D]

// ---------------------------------------------------------------------------
// SGEMM + bias: C[M,N] = A[M,K] @ B[K,N] + bias[N]
// 128x128 block tile, BK=8, 256 threads, 8x8 microtile, software-pipelined
// global loads. Requires M%128==0, N%128==0, K%8==0 (true for all our shapes).
// ---------------------------------------------------------------------------
__global__ __launch_bounds__(256) void sgemm_bias(const float* __restrict__ A,
                                                  const float* __restrict__ Bm,
                                                  const float* __restrict__ bias,
                                                  float* __restrict__ C,
                                                  int M, int N, int K)
{
    __shared__ float As[8][128];   // transposed: As[k][m]
    __shared__ float Bs[8][128];   // Bs[k][n]

    const int t  = threadIdx.x;
    const int tx = t & 15;
    const int ty = t >> 4;
    const int m0 = blockIdx.y * 128;
    const int n0 = blockIdx.x * 128;

    float acc[8][8];
#pragma unroll
    for (int i = 0; i < 8; i++)
#pragma unroll
        for (int j = 0; j < 8; j++) acc[i][j] = 0.0f;

    const int arow = t >> 1;          // 0..127
    const int acol = (t & 1) * 4;     // 0 or 4
    const int brow = t >> 5;          // 0..7
    const int bcol = (t & 31) * 4;    // 0..124

    const float* Ap = A  + (size_t)(m0 + arow) * K + acol;
    const float* Bp = Bm + (size_t)brow * N + n0 + bcol;

    // prefetch first tiles
    float4 av = *(const float4*)(Ap);
    float4 bv = *(const float4*)(Bp);

    for (int k0 = 0; k0 < K; k0 += 8) {
        As[acol + 0][arow] = av.x;
        As[acol + 1][arow] = av.y;
        As[acol + 2][arow] = av.z;
        As[acol + 3][arow] = av.w;
        *(float4*)&Bs[brow][bcol] = bv;
        __syncthreads();

        if (k0 + 8 < K) {
            av = *(const float4*)(Ap + (k0 + 8));
            bv = *(const float4*)(Bp + (size_t)(k0 + 8) * N);
        }

#pragma unroll
        for (int kk = 0; kk < 8; kk++) {
            float a[8], b[8];
            *(float4*)&a[0] = *(const float4*)&As[kk][ty * 4];
            *(float4*)&a[4] = *(const float4*)&As[kk][64 + ty * 4];
            *(float4*)&b[0] = *(const float4*)&Bs[kk][tx * 4];
            *(float4*)&b[4] = *(const float4*)&Bs[kk][64 + tx * 4];
#pragma unroll
            for (int i = 0; i < 8; i++)
#pragma unroll
                for (int j = 0; j < 8; j++)
                    acc[i][j] += a[i] * b[j];
        }
        __syncthreads();
    }

    // epilogue: add bias, float4 stores
#pragma unroll
    for (int ih = 0; ih < 2; ih++) {
#pragma unroll
        for (int ii = 0; ii < 4; ii++) {
            const int i = ih * 4 + ii;
            const int r = m0 + ih * 64 + ty * 4 + ii;
#pragma unroll
            for (int jh = 0; jh < 2; jh++) {
                const int c = n0 + jh * 64 + tx * 4;
                float4 bvv = *(const float4*)&bias[c];
                float4 res;
                res.x = acc[i][jh * 4 + 0] + bvv.x;
                res.y = acc[i][jh * 4 + 1] + bvv.y;
                res.z = acc[i][jh * 4 + 2] + bvv.z;
                res.w = acc[i][jh * 4 + 3] + bvv.w;
                *(float4*)&C[(size_t)r * N + c] = res;
            }
        }
    }
}

// ---------------------------------------------------------------------------
// Flash attention, fp32, one CTA per (b, h, 64-row q tile).
// qkv layout [B,T,3D]; q at col h*64, k at D + h*64, v at 2D + h*64.
// Online softmax. Cols >= len masked (-1e30 -> exp underflows to exact 0);
// rows >= len written as 0 (matches reference softmax*mask semantics).
// ---------------------------------------------------------------------------
#define AP 68   // padded row stride (floats), keeps float4 alignment, de-conflicts

__global__ __launch_bounds__(256) void flash_attn(const float* __restrict__ qkv,
                                                  const int* __restrict__ lengths,
                                                  float* __restrict__ out)
{
    extern __shared__ float sm[];
    float* QsT = sm;                 // [64][AP]  (d-major: QsT[d*AP + r])
    float* KsT = sm + 64 * AP;       // [64][AP]  (d-major), reused as P [c][r]
    float* Vs  = sm + 2 * 64 * AP;   // [64][AP]  (c-major: Vs[c*AP + d])

    const int t  = threadIdx.x;
    const int tx = t & 15;           // kv-col group / Dh-col group
    const int ty = t >> 4;           // q-row group
    const int bh = blockIdx.x;
    const int b  = bh >> 4;
    const int h  = bh & 15;
    const int r0 = blockIdx.y * 64;
    const int l  = lengths[b];

    const float* base = qkv + (size_t)b * TT * D3 + h * DH;

    // ---- load Q (scaled by 1/sqrt(Dh) = 0.125), transposed into QsT[d][r]
    {
        const int lr = t >> 2;             // 0..63 row
        const int d0 = (t & 3) * 16;       // d chunk start
        const float* qp = base + (size_t)(r0 + lr) * D3 + d0;
#pragma unroll
        for (int u = 0; u < 4; u++) {
            float4 v = *(const float4*)(qp + u * 4);
            QsT[(d0 + u * 4 + 0) * AP + lr] = v.x * 0.125f;
            QsT[(d0 + u * 4 + 1) * AP + lr] = v.y * 0.125f;
            QsT[(d0 + u * 4 + 2) * AP + lr] = v.z * 0.125f;
            QsT[(d0 + u * 4 + 3) * AP + lr] = v.w * 0.125f;
        }
    }

    float m_i[4], l_i[4], o[4][4];
#pragma unroll
    for (int i = 0; i < 4; i++) {
        m_i[i] = -1e30f;
        l_i[i] = 0.0f;
#pragma unroll
        for (int j = 0; j < 4; j++) o[i][j] = 0.0f;
    }

    const int ntiles = (l + 63) >> 6;   // tiles fully past len contribute 0
    for (int kt = 0; kt < ntiles; kt++) {
        const int c0 = kt * 64;

        // ---- load K transposed (KsT[d][c]) and V natural (Vs[c][d])
        {
            const int lr = t >> 2;
            const int d0 = (t & 3) * 16;
            const float* kp = base + DD     + (size_t)(c0 + lr) * D3 + d0;
            const float* vp = base + 2 * DD + (size_t)(c0 + lr) * D3 + d0;
#pragma unroll
            for (int u = 0; u < 4; u++) {
                float4 kv = *(const float4*)(kp + u * 4);
                KsT[(d0 + u * 4 + 0) * AP + lr] = kv.x;
                KsT[(d0 + u * 4 + 1) * AP + lr] = kv.y;
                KsT[(d0 + u * 4 + 2) * AP + lr] = kv.z;
                KsT[(d0 + u * 4 + 3) * AP + lr] = kv.w;
                float4 vv = *(const float4*)(vp + u * 4);
                *(float4*)&Vs[lr * AP + d0 + u * 4] = vv;
            }
        }
        __syncthreads();   // K/V (and Q on iter 0) visible

        // ---- S = (Q*scale) @ K^T, 4x4 per thread
        float s[4][4];
#pragma unroll
        for (int i = 0; i < 4; i++)
#pragma unroll
            for (int j = 0; j < 4; j++) s[i][j] = 0.0f;

#pragma unroll
        for (int d = 0; d < 64; d++) {
            float4 q4 = *(const float4*)&QsT[d * AP + ty * 4];
            float4 k4 = *(const float4*)&KsT[d * AP + tx * 4];
            float qa[4] = {q4.x, q4.y, q4.z, q4.w};
            float ka[4] = {k4.x, k4.y, k4.z, k4.w};
#pragma unroll
            for (int i = 0; i < 4; i++)
#pragma unroll
                for (int j = 0; j < 4; j++)
                    s[i][j] += qa[i] * ka[j];
        }

        // ---- column mask (only possible on the last tile)
        if (c0 + 64 > l) {
#pragma unroll
            for (int j = 0; j < 4; j++) {
                if (c0 + tx * 4 + j >= l) {
#pragma unroll
                    for (int i = 0; i < 4; i++) s[i][j] = -1e30f;
                }
            }
        }

        // ---- online softmax (row spans 16 contiguous lanes -> shfl_xor <=8)
#pragma unroll
        for (int i = 0; i < 4; i++) {
            float rm = fmaxf(fmaxf(s[i][0], s[i][1]), fmaxf(s[i][2], s[i][3]));
            rm = fmaxf(rm, __shfl_xor_sync(0xffffffffu, rm, 1));
            rm = fmaxf(rm, __shfl_xor_sync(0xffffffffu, rm, 2));
            rm = fmaxf(rm, __shfl_xor_sync(0xffffffffu, rm, 4));
            rm = fmaxf(rm, __shfl_xor_sync(0xffffffffu, rm, 8));
            float mnew = fmaxf(m_i[i], rm);
            float corr = __expf(m_i[i] - mnew);
            m_i[i] = mnew;
            float rs = 0.0f;
#pragma unroll
            for (int j = 0; j < 4; j++) {
                s[i][j] = __expf(s[i][j] - mnew);
                rs += s[i][j];
            }
            rs += __shfl_xor_sync(0xffffffffu, rs, 1);
            rs += __shfl_xor_sync(0xffffffffu, rs, 2);
            rs += __shfl_xor_sync(0xffffffffu, rs, 4);
            rs += __shfl_xor_sync(0xffffffffu, rs, 8);
            l_i[i] = l_i[i] * corr + rs;
#pragma unroll
            for (int j = 0; j < 4; j++) o[i][j] *= corr;
        }

        __syncthreads();   // all reads of KsT done before overwriting with P

        // ---- store P into KsT space as P[c][r] (c-major) for the PV pass
        float* Pst = KsT;
#pragma unroll
        for (int j = 0; j < 4; j++) {
            float4 pv = make_float4(s[0][j], s[1][j], s[2][j], s[3][j]);
            *(float4*)&Pst[(tx * 4 + j) * AP + ty * 4] = pv;
        }
        __syncthreads();   // P visible

        // ---- O += P @ V
#pragma unroll
        for (int c = 0; c < 64; c++) {
            float4 p4 = *(const float4*)&Pst[c * AP + ty * 4];
            float4 v4 = *(const float4*)&Vs[c * AP + tx * 4];
            float pa[4] = {p4.x, p4.y, p4.z, p4.w};
            float va[4] = {v4.x, v4.y, v4.z, v4.w};
#pragma unroll
            for (int i = 0; i < 4; i++)
#pragma unroll
                for (int j = 0; j < 4; j++)
                    o[i][j] += pa[i] * va[j];
        }
        __syncthreads();   // PV reads done before next tile load
    }

    // ---- writeout: divide by softmax denom, zero rows >= len
    float* ob = out + (size_t)b * TT * DD + h * DH;
#pragma unroll
    for (int i = 0; i < 4; i++) {
        const int r = r0 + ty * 4 + i;
        const float inv = (r < l) ? (1.0f / l_i[i]) : 0.0f;
        float4 res = make_float4(o[i][0] * inv, o[i][1] * inv,
                                 o[i][2] * inv, o[i][3] * inv);
        *(float4*)&ob[(size_t)r * DD + tx * 4] = res;
    }
}

// ---------------------------------------------------------------------------
// Launch: qkv-proj GEMM -> flash attention -> output-proj GEMM
// ---------------------------------------------------------------------------
extern "C" void kernel_launch(void* const* d_in, const int* in_sizes, int n_in,
                              void* d_out, int out_size)
{
    const float* x      = (const float*)d_in[0];   // [8,1024,1024]
    const int*   lens   = (const int*)  d_in[1];   // [8]
    const float* w_qkv  = (const float*)d_in[2];   // [1024,3072]
    const float* b_qkv  = (const float*)d_in[3];   // [3072]
    const float* w_o    = (const float*)d_in[4];   // [1024,1024]
    const float* b_o    = (const float*)d_in[5];   // [1024]
    float*       out    = (float*)d_out;           // [8,1024,1024]

    void* qkv_ptr = nullptr;
    void* attn_ptr = nullptr;
    cudaGetSymbolAddress(&qkv_ptr, g_qkv);
    cudaGetSymbolAddress(&attn_ptr, g_attn);
    float* g_qkv_p  = (float*)qkv_ptr;
    float* g_attn_p = (float*)attn_ptr;

    const int M = BB * TT;   // 8192

    // GEMM1: [8192,1024] @ [1024,3072] + b_qkv
    {
        dim3 grid(D3 / 128, M / 128);
        sgemm_bias<<<grid, 256>>>(x, w_qkv, b_qkv, g_qkv_p, M, D3, DD);
    }

    // Flash attention: grid (B*H, T/64)
    {
        const int smem = 3 * 64 * AP * (int)sizeof(float);  // 52224 B
        cudaFuncSetAttribute(flash_attn,
                             cudaFuncAttributeMaxDynamicSharedMemorySize, smem);
        dim3 grid(BB * HH, TT / 64);
        flash_attn<<<grid, 256, smem>>>(g_qkv_p, lens, g_attn_p);
    }

    // GEMM2: [8192,1024] @ [1024,1024] + b_o -> out
    {
        dim3 grid(DD / 128, M / 128);
        sgemm_bias<<<grid, 256>>>(g_attn_p, w_o, b_o, out, M, DD, DD);
    }
}